// round 1
// baseline (speedup 1.0000x reference)
#include <cuda_runtime.h>
#include <math.h>

// Problem constants
#define CDIM   1024
#define TSEQ   2048
#define BBATCH 2
#define NHEAD  16
#define HDIM   64
#define MROWS  (BBATCH * TSEQ)   // 4096

// Scratch (allocation-free rule: __device__ globals)
__device__ float g_Q [MROWS * CDIM];
__device__ float g_K [MROWS * CDIM];
__device__ float g_V [MROWS * CDIM];
__device__ float g_AO[MROWS * CDIM];

// ---------------------------------------------------------------------------
// GEMM: C[M,N] = A[M,K] @ W[K,N] + bias[N]   (all row-major, fp32)
// 128x128 tile, BK=16, 256 threads, 8x8 per thread.
// ---------------------------------------------------------------------------
__global__ __launch_bounds__(256, 2)
void gemm_bias_kernel(const float* __restrict__ A,
                      const float* __restrict__ W,
                      const float* __restrict__ bias,
                      float* __restrict__ C,
                      int M, int N, int K)
{
    __shared__ float As[16][132];   // k-major (transposed), padded
    __shared__ float Bs[16][128];

    const int tid = threadIdx.x;
    const int tx  = tid & 15;       // n
    const int ty  = tid >> 4;       // m
    const int bm  = blockIdx.y;
    const int bn  = blockIdx.x;

    const float* Ab = A + (size_t)bm * 128 * K;
    const float* Wb = W + (size_t)bn * 128;

    float acc[8][8];
#pragma unroll
    for (int m = 0; m < 8; m++)
#pragma unroll
        for (int n = 0; n < 8; n++) acc[m][n] = 0.0f;

    for (int k0 = 0; k0 < K; k0 += 16) {
        // Load A tile: 128x16 = 512 float4
#pragma unroll
        for (int i = 0; i < 2; i++) {
            int f4  = tid + i * 256;
            int row = f4 >> 2;
            int c4  = f4 & 3;
            float4 v = *reinterpret_cast<const float4*>(Ab + (size_t)row * K + k0 + c4 * 4);
            As[c4 * 4 + 0][row] = v.x;
            As[c4 * 4 + 1][row] = v.y;
            As[c4 * 4 + 2][row] = v.z;
            As[c4 * 4 + 3][row] = v.w;
        }
        // Load W tile: 16x128 = 512 float4
#pragma unroll
        for (int i = 0; i < 2; i++) {
            int f4  = tid + i * 256;
            int row = f4 >> 5;
            int c   = (f4 & 31) * 4;
            *reinterpret_cast<float4*>(&Bs[row][c]) =
                *reinterpret_cast<const float4*>(Wb + (size_t)(k0 + row) * N + c);
        }
        __syncthreads();

#pragma unroll
        for (int k = 0; k < 16; k++) {
            float ra[8], rb[8];
            *reinterpret_cast<float4*>(ra)     = *reinterpret_cast<const float4*>(&As[k][ty * 8]);
            *reinterpret_cast<float4*>(ra + 4) = *reinterpret_cast<const float4*>(&As[k][ty * 8 + 4]);
            *reinterpret_cast<float4*>(rb)     = *reinterpret_cast<const float4*>(&Bs[k][tx * 8]);
            *reinterpret_cast<float4*>(rb + 4) = *reinterpret_cast<const float4*>(&Bs[k][tx * 8 + 4]);
#pragma unroll
            for (int m = 0; m < 8; m++)
#pragma unroll
                for (int n = 0; n < 8; n++)
                    acc[m][n] = fmaf(ra[m], rb[n], acc[m][n]);
        }
        __syncthreads();
    }

    const int col0 = bn * 128 + tx * 8;
    float bl[8];
#pragma unroll
    for (int n = 0; n < 8; n++) bl[n] = bias[col0 + n];

#pragma unroll
    for (int m = 0; m < 8; m++) {
        const int row = bm * 128 + ty * 8 + m;
        float* Crow = C + (size_t)row * N + col0;
        float4 v0, v1;
        v0.x = acc[m][0] + bl[0]; v0.y = acc[m][1] + bl[1];
        v0.z = acc[m][2] + bl[2]; v0.w = acc[m][3] + bl[3];
        v1.x = acc[m][4] + bl[4]; v1.y = acc[m][5] + bl[5];
        v1.z = acc[m][6] + bl[6]; v1.w = acc[m][7] + bl[7];
        *reinterpret_cast<float4*>(Crow)     = v0;
        *reinterpret_cast<float4*>(Crow + 4) = v1;
    }
}

// ---------------------------------------------------------------------------
// Attention. Valid keys for query i: j in [max(0,(i/128-1)*128), i]  (<=256).
// One CTA per (b, h, 128-query block). 256 threads = 8 warps, warp-per-query.
// SMEM: K/V tiles (256x64, row stride 65 -> conflict-free), Q tile, P arrays.
// ---------------------------------------------------------------------------
#define KSTRIDE 65
__global__ __launch_bounds__(256, 1)
void attn_kernel(const float* __restrict__ Q,
                 const float* __restrict__ K,
                 const float* __restrict__ V,
                 float* __restrict__ O,
                 float* __restrict__ attn)   // may be nullptr
{
    const int qblk = blockIdx.x;   // 0..15
    const int h    = blockIdx.y;   // 0..15
    const int b    = blockIdx.z;   // 0..1

    const int kbase = (qblk == 0) ? 0 : (qblk - 1) * 128;
    const int nk    = (qblk == 0) ? 128 : 256;

    extern __shared__ float sh[];
    float* Ks = sh;                         // 256*65
    float* Vs = Ks + 256 * KSTRIDE;         // 256*65
    float* Qs = Vs + 256 * KSTRIDE;         // 128*64
    float* Ps = Qs + 128 * HDIM;            // 8*256

    const int tid  = threadIdx.x;
    const int lane = tid & 31;
    const int w    = tid >> 5;

    const float* Kg = K + ((size_t)b * TSEQ + kbase) * CDIM + h * HDIM;
    const float* Vg = V + ((size_t)b * TSEQ + kbase) * CDIM + h * HDIM;
    for (int idx = tid; idx < nk * HDIM; idx += 256) {
        int r = idx >> 6, c = idx & 63;
        Ks[r * KSTRIDE + c] = Kg[(size_t)r * CDIM + c];
        Vs[r * KSTRIDE + c] = Vg[(size_t)r * CDIM + c];
    }
    const float* Qg = Q + ((size_t)b * TSEQ + qblk * 128) * CDIM + h * HDIM;
    for (int idx = tid; idx < 128 * HDIM; idx += 256) {
        int r = idx >> 6, c = idx & 63;
        Qs[idx] = Qg[(size_t)r * CDIM + c];
    }
    __syncthreads();

    const float slope = exp2f(-0.5f * (float)(h + 1));
    float* pw = Ps + w * 256;

    for (int iq = w; iq < 128; iq += 8) {
        const int i = qblk * 128 + iq;

        // query row into registers
        float qr[64];
        const float* qrow = Qs + iq * HDIM;
#pragma unroll
        for (int c = 0; c < 64; c++) qr[c] = qrow[c];

        // scores: 8 keys per lane
        float s[8];
#pragma unroll
        for (int r = 0; r < 8; r++) {
            const int jl = lane + 32 * r;
            const int j  = kbase + jl;
            if (jl < nk && j <= i) {
                const float* krow = Ks + jl * KSTRIDE;
                float d = 0.0f;
#pragma unroll
                for (int c = 0; c < 64; c++) d = fmaf(qr[c], krow[c], d);
                s[r] = d * 0.125f + slope * (float)(i - j);
            } else {
                s[r] = -INFINITY;
            }
        }

        // warp softmax
        float m = s[0];
#pragma unroll
        for (int r = 1; r < 8; r++) m = fmaxf(m, s[r]);
#pragma unroll
        for (int off = 16; off > 0; off >>= 1)
            m = fmaxf(m, __shfl_xor_sync(0xffffffffu, m, off));

        float e[8];
        float sum = 0.0f;
#pragma unroll
        for (int r = 0; r < 8; r++) { e[r] = expf(s[r] - m); sum += e[r]; }
#pragma unroll
        for (int off = 16; off > 0; off >>= 1)
            sum += __shfl_xor_sync(0xffffffffu, sum, off);
        const float inv = 1.0f / sum;

#pragma unroll
        for (int r = 0; r < 8; r++) {
            const int jl = lane + 32 * r;
            const float p = e[r] * inv;
            pw[jl] = p;
            if (attn) {
                const int j = kbase + jl;
                if (jl < nk && j <= i)
                    attn[(((size_t)(b * NHEAD + h) * TSEQ + i) * TSEQ) + j] = p;
            }
        }
        __syncwarp();

        // PV: each lane accumulates dims {lane, lane+32}
        float o0 = 0.0f, o1 = 0.0f;
        for (int j = 0; j < nk; j++) {
            const float p = pw[j];
            o0 = fmaf(p, Vs[j * KSTRIDE + lane],      o0);
            o1 = fmaf(p, Vs[j * KSTRIDE + lane + 32], o1);
        }
        float* Og = O + ((size_t)b * TSEQ + i) * CDIM + h * HDIM;
        Og[lane]      = o0;
        Og[lane + 32] = o1;
        __syncwarp();
    }
}

// ---------------------------------------------------------------------------
extern "C" void kernel_launch(void* const* d_in, const int* in_sizes, int n_in,
                              void* d_out, int out_size)
{
    const float* x  = (const float*)d_in[0];
    const float* Wq = (const float*)d_in[1];
    const float* bq = (const float*)d_in[2];
    const float* Wk = (const float*)d_in[3];
    const float* bk = (const float*)d_in[4];
    const float* Wv = (const float*)d_in[5];
    const float* bv = (const float*)d_in[6];
    const float* Wo = (const float*)d_in[7];
    const float* bo = (const float*)d_in[8];
    float* out = (float*)d_out;

    float *Qp, *Kp, *Vp, *AOp;
    cudaGetSymbolAddress((void**)&Qp,  g_Q);
    cudaGetSymbolAddress((void**)&Kp,  g_K);
    cudaGetSymbolAddress((void**)&Vp,  g_V);
    cudaGetSymbolAddress((void**)&AOp, g_AO);

    const int M = MROWS, N = CDIM, Kk = CDIM;
    dim3 ggrid(N / 128, M / 128);

    gemm_bias_kernel<<<ggrid, 256>>>(x, Wq, bq, Qp, M, N, Kk);
    gemm_bias_kernel<<<ggrid, 256>>>(x, Wk, bk, Kp, M, N, Kk);
    gemm_bias_kernel<<<ggrid, 256>>>(x, Wv, bv, Vp, M, N, Kk);

    // Does the harness want the attention matrix too? (reference returns a tuple)
    float* attn = nullptr;
    const long long out_elems = (long long)MROWS * CDIM;          // 4,194,304
    if ((long long)out_size > out_elems) {
        attn = out + out_elems;
        cudaMemsetAsync(attn, 0,
                        (size_t)BBATCH * NHEAD * TSEQ * TSEQ * sizeof(float), 0);
    }

    const size_t ATT_SHM = (size_t)(2 * 256 * KSTRIDE + 128 * HDIM + 8 * 256) * sizeof(float);
    cudaFuncSetAttribute(attn_kernel, cudaFuncAttributeMaxDynamicSharedMemorySize, (int)ATT_SHM);
    dim3 agrid(TSEQ / 128, NHEAD, BBATCH);
    attn_kernel<<<agrid, 256, ATT_SHM>>>(Qp, Kp, Vp, AOp, attn);

    gemm_bias_kernel<<<ggrid, 256>>>(AOp, Wo, bo, out, M, N, Kk);
}

// round 6
// speedup vs baseline: 1.6030x; 1.6030x over previous
#include <cuda_runtime.h>
#include <cuda_bf16.h>
#include <cstdint>
#include <math.h>

// Problem constants
#define CDIM   1024
#define TSEQ   2048
#define BBATCH 2
#define NHEAD  16
#define HDIM   64
#define MROWS  (BBATCH * TSEQ)   // 4096

// ---------------------------------------------------------------------------
// Scratch (__device__ globals; allocation-free rule)
// ---------------------------------------------------------------------------
__device__ float g_Q [MROWS * CDIM];
__device__ float g_K [MROWS * CDIM];
__device__ float g_V [MROWS * CDIM];
__device__ float g_AO[MROWS * CDIM];

// bf16 hi/lo splits of activations and transposed weights
__device__ __nv_bfloat16 g_xh [MROWS * CDIM];
__device__ __nv_bfloat16 g_xl [MROWS * CDIM];
__device__ __nv_bfloat16 g_aoh[MROWS * CDIM];
__device__ __nv_bfloat16 g_aol[MROWS * CDIM];
__device__ __nv_bfloat16 g_wh [4][CDIM * CDIM];  // W^T hi  [n][k]
__device__ __nv_bfloat16 g_wl [4][CDIM * CDIM];  // W^T lo  [n][k]

__device__ __forceinline__ uint32_t smem_u32(const void* p) {
    uint32_t a;
    asm("{ .reg .u64 t; cvta.to.shared.u64 t, %1; cvt.u32.u64 %0, t; }" : "=r"(a) : "l"(p));
    return a;
}

// ---------------------------------------------------------------------------
// Split/convert kernels
// ---------------------------------------------------------------------------
__global__ void split_fp32_kernel(const float* __restrict__ in,
                                  __nv_bfloat16* __restrict__ h,
                                  __nv_bfloat16* __restrict__ l, int n4)
{
    int i = blockIdx.x * 256 + threadIdx.x;
    if (i >= n4) return;
    float4 v = reinterpret_cast<const float4*>(in)[i];
    __nv_bfloat16 hx = __float2bfloat16(v.x), hy = __float2bfloat16(v.y);
    __nv_bfloat16 hz = __float2bfloat16(v.z), hw = __float2bfloat16(v.w);
    __nv_bfloat16 lx = __float2bfloat16(v.x - __bfloat162float(hx));
    __nv_bfloat16 ly = __float2bfloat16(v.y - __bfloat162float(hy));
    __nv_bfloat16 lz = __float2bfloat16(v.z - __bfloat162float(hz));
    __nv_bfloat16 lw = __float2bfloat16(v.w - __bfloat162float(hw));
    reinterpret_cast<__nv_bfloat162*>(h)[i * 2]     = __nv_bfloat162(hx, hy);
    reinterpret_cast<__nv_bfloat162*>(h)[i * 2 + 1] = __nv_bfloat162(hz, hw);
    reinterpret_cast<__nv_bfloat162*>(l)[i * 2]     = __nv_bfloat162(lx, ly);
    reinterpret_cast<__nv_bfloat162*>(l)[i * 2 + 1] = __nv_bfloat162(lz, lw);
}

// W[k][n] (1024x1024 fp32) -> Bh/Bl[n][k] bf16 (transposed split)
__global__ void split_transpose_kernel(const float* __restrict__ W,
                                       __nv_bfloat16* __restrict__ Bh,
                                       __nv_bfloat16* __restrict__ Bl)
{
    __shared__ float t[32][33];
    const int n0 = blockIdx.x * 32, k0 = blockIdx.y * 32;
    const int tx = threadIdx.x, ty = threadIdx.y;
#pragma unroll
    for (int dy = 0; dy < 32; dy += 8)
        t[ty + dy][tx] = W[(size_t)(k0 + ty + dy) * CDIM + n0 + tx];
    __syncthreads();
#pragma unroll
    for (int dy = 0; dy < 32; dy += 8) {
        const int n = n0 + ty + dy;
        const float v = t[tx][ty + dy];
        __nv_bfloat16 h = __float2bfloat16(v);
        __nv_bfloat16 l = __float2bfloat16(v - __bfloat162float(h));
        Bh[(size_t)n * CDIM + k0 + tx] = h;
        Bl[(size_t)n * CDIM + k0 + tx] = l;
    }
}

// ---------------------------------------------------------------------------
// HMMA GEMM: C[M,1024] = (Ah+Al)[M,1024] @ (Bh+Bl)^T + bias
// mma.sync.m16n8k16 bf16, error-compensated (3 passes: hh + hl + lh).
// CTA tile 128(m) x 64(n), BK=32, 256 threads = 8 warps (4m x 2n), warp 32x32.
// SMEM rows pack hi|lo 32+32 bf16 = 128B, chunk-XOR swizzle (c ^ (r&7)).
// cp.async 2-stage pipeline.
// ---------------------------------------------------------------------------
#define BKC     32
#define NITER   (CDIM / BKC)          // 32
#define SM_A_SZ (128 * 128)           // 16 KB
#define SM_B_SZ (64 * 128)            // 8 KB

__device__ __forceinline__ void cp_async16(uint32_t dst, const void* src) {
    asm volatile("cp.async.cg.shared.global [%0], [%1], 16;" :: "r"(dst), "l"(src));
}
__device__ __forceinline__ void cp_commit() {
    asm volatile("cp.async.commit_group;");
}
__device__ __forceinline__ void cp_wait1() {
    asm volatile("cp.async.wait_group 1;");
}

__device__ __forceinline__ void ldsm_x4(uint32_t* r, uint32_t addr) {
    asm volatile("ldmatrix.sync.aligned.m8n8.x4.shared.b16 {%0,%1,%2,%3}, [%4];"
                 : "=r"(r[0]), "=r"(r[1]), "=r"(r[2]), "=r"(r[3]) : "r"(addr));
}
__device__ __forceinline__ void mma_bf16(float* c, const uint32_t* a, const uint32_t* b) {
    asm volatile("mma.sync.aligned.m16n8k16.row.col.f32.bf16.bf16.f32 "
                 "{%0,%1,%2,%3}, {%4,%5,%6,%7}, {%8,%9}, {%0,%1,%2,%3};"
                 : "+f"(c[0]), "+f"(c[1]), "+f"(c[2]), "+f"(c[3])
                 : "r"(a[0]), "r"(a[1]), "r"(a[2]), "r"(a[3]), "r"(b[0]), "r"(b[1]));
}

__global__ __launch_bounds__(256, 2)
void gemm_hmma_kernel(const __nv_bfloat16* __restrict__ Ah,
                      const __nv_bfloat16* __restrict__ Al,
                      const __nv_bfloat16* __restrict__ Bh,
                      const __nv_bfloat16* __restrict__ Bl,
                      const float* __restrict__ bias,
                      float* __restrict__ C)
{
    __shared__ __align__(128) char smA[2][SM_A_SZ];
    __shared__ __align__(128) char smB[2][SM_B_SZ];

    const int tid  = threadIdx.x;
    const int lane = tid & 31;
    const int wrp  = tid >> 5;
    const int wm   = (wrp >> 1) * 32;   // warp m offset (0,32,64,96)
    const int wn   = (wrp & 1) * 32;    // warp n offset (0,32)
    const int bm   = blockIdx.y;        // 0..31
    const int bn   = blockIdx.x;        // 0..15

    const uint32_t sA[2] = { smem_u32(smA[0]), smem_u32(smA[1]) };
    const uint32_t sB[2] = { smem_u32(smB[0]), smem_u32(smB[1]) };

    const __nv_bfloat16* Agh = Ah + (size_t)(bm * 128) * CDIM;
    const __nv_bfloat16* Agl = Al + (size_t)(bm * 128) * CDIM;
    const __nv_bfloat16* Bgh = Bh + (size_t)(bn * 64) * CDIM;
    const __nv_bfloat16* Bgl = Bl + (size_t)(bn * 64) * CDIM;

    // Issue cp.async loads for K-iteration kI into stage s.
    auto issue_stage = [&](int kI, int s) {
        if (kI < NITER) {
            const int k0 = kI * BKC;
            // A: 128 rows x 8 chunks (0-3: hi k0..31, 4-7: lo k0..31) = 1024 chunks
#pragma unroll
            for (int i = 0; i < 4; i++) {
                const int idx = tid + i * 256;
                const int r = idx >> 3, c = idx & 7;
                const __nv_bfloat16* src =
                    ((c < 4) ? Agh : Agl) + (size_t)r * CDIM + k0 + (c & 3) * 8;
                cp_async16(sA[s] + r * 128 + 16 * (c ^ (r & 7)), src);
            }
            // B: 64 rows x 8 chunks = 512 chunks
#pragma unroll
            for (int i = 0; i < 2; i++) {
                const int idx = tid + i * 256;
                const int r = idx >> 3, c = idx & 7;
                const __nv_bfloat16* src =
                    ((c < 4) ? Bgh : Bgl) + (size_t)r * CDIM + k0 + (c & 3) * 8;
                cp_async16(sB[s] + r * 128 + 16 * (c ^ (r & 7)), src);
            }
        }
        cp_commit();
    };

    float acc[2][4][4];
#pragma unroll
    for (int mt = 0; mt < 2; mt++)
#pragma unroll
        for (int ng = 0; ng < 4; ng++)
#pragma unroll
            for (int j = 0; j < 4; j++) acc[mt][ng][j] = 0.0f;

    issue_stage(0, 0);
    issue_stage(1, 1);

    for (int kI = 0; kI < NITER; kI++) {
        const int s = kI & 1;
        cp_wait1();
        __syncthreads();

#pragma unroll
        for (int kk = 0; kk < 2; kk++) {
            // A fragments: [half][mtile][4]
            uint32_t afr[2][2][4];
#pragma unroll
            for (int h = 0; h < 2; h++)
#pragma unroll
                for (int mt = 0; mt < 2; mt++) {
                    const int row = wm + mt * 16 + (lane & 15);
                    const int ch  = h * 4 + kk * 2 + (lane >> 4);
                    ldsm_x4(afr[h][mt], sA[s] + row * 128 + 16 * (ch ^ (row & 7)));
                }
            // B fragments: [half][nb] -> regs {b0g0,b1g0,b0g1,b1g1}
            uint32_t bfr[2][2][4];
#pragma unroll
            for (int h = 0; h < 2; h++)
#pragma unroll
                for (int nb = 0; nb < 2; nb++) {
                    const int nrow = wn + nb * 16 + (lane & 7) + ((lane >> 4) & 1) * 8;
                    const int ch   = h * 4 + kk * 2 + ((lane >> 3) & 1);
                    ldsm_x4(bfr[h][nb], sB[s] + nrow * 128 + 16 * (ch ^ (nrow & 7)));
                }
#pragma unroll
            for (int mt = 0; mt < 2; mt++)
#pragma unroll
                for (int ng = 0; ng < 4; ng++) {
                    const uint32_t* bh2 = &bfr[0][ng >> 1][(ng & 1) * 2];
                    const uint32_t* bl2 = &bfr[1][ng >> 1][(ng & 1) * 2];
                    mma_bf16(acc[mt][ng], afr[0][mt], bh2);   // Ah*Bh
                    mma_bf16(acc[mt][ng], afr[0][mt], bl2);   // Ah*Bl
                    mma_bf16(acc[mt][ng], afr[1][mt], bh2);   // Al*Bh
                }
        }
        __syncthreads();
        issue_stage(kI + 2, s);
    }

    // Epilogue: bias + store
    const int g = lane >> 2, tq = lane & 3;
#pragma unroll
    for (int mt = 0; mt < 2; mt++) {
#pragma unroll
        for (int ng = 0; ng < 4; ng++) {
            const int col = bn * 64 + wn + ng * 8 + tq * 2;
            const float b0 = bias[col], b1 = bias[col + 1];
            const int r0 = bm * 128 + wm + mt * 16 + g;
            float2 v0 = make_float2(acc[mt][ng][0] + b0, acc[mt][ng][1] + b1);
            float2 v1 = make_float2(acc[mt][ng][2] + b0, acc[mt][ng][3] + b1);
            *reinterpret_cast<float2*>(C + (size_t)r0 * CDIM + col)       = v0;
            *reinterpret_cast<float2*>(C + (size_t)(r0 + 8) * CDIM + col) = v1;
        }
    }
}

// ---------------------------------------------------------------------------
// Attention (unchanged). Valid keys for query i:
// j in [max(0,(i/128-1)*128), i]  (<=256).
// ---------------------------------------------------------------------------
#define KSTRIDE 65
__global__ __launch_bounds__(256, 1)
void attn_kernel(const float* __restrict__ Q,
                 const float* __restrict__ K,
                 const float* __restrict__ V,
                 float* __restrict__ O,
                 float* __restrict__ attn)
{
    const int qblk = blockIdx.x;
    const int h    = blockIdx.y;
    const int b    = blockIdx.z;

    const int kbase = (qblk == 0) ? 0 : (qblk - 1) * 128;
    const int nk    = (qblk == 0) ? 128 : 256;

    extern __shared__ float sh[];
    float* Ks = sh;
    float* Vs = Ks + 256 * KSTRIDE;
    float* Qs = Vs + 256 * KSTRIDE;
    float* Ps = Qs + 128 * HDIM;

    const int tid  = threadIdx.x;
    const int lane = tid & 31;
    const int w    = tid >> 5;

    const float* Kg = K + ((size_t)b * TSEQ + kbase) * CDIM + h * HDIM;
    const float* Vg = V + ((size_t)b * TSEQ + kbase) * CDIM + h * HDIM;
    for (int idx = tid; idx < nk * HDIM; idx += 256) {
        int r = idx >> 6, c = idx & 63;
        Ks[r * KSTRIDE + c] = Kg[(size_t)r * CDIM + c];
        Vs[r * KSTRIDE + c] = Vg[(size_t)r * CDIM + c];
    }
    const float* Qg = Q + ((size_t)b * TSEQ + qblk * 128) * CDIM + h * HDIM;
    for (int idx = tid; idx < 128 * HDIM; idx += 256) {
        int r = idx >> 6, c = idx & 63;
        Qs[idx] = Qg[(size_t)r * CDIM + c];
    }
    __syncthreads();

    const float slope = exp2f(-0.5f * (float)(h + 1));
    float* pw = Ps + w * 256;

    for (int iq = w; iq < 128; iq += 8) {
        const int i = qblk * 128 + iq;

        float qr[64];
        const float* qrow = Qs + iq * HDIM;
#pragma unroll
        for (int c = 0; c < 64; c++) qr[c] = qrow[c];

        float s[8];
#pragma unroll
        for (int r = 0; r < 8; r++) {
            const int jl = lane + 32 * r;
            const int j  = kbase + jl;
            if (jl < nk && j <= i) {
                const float* krow = Ks + jl * KSTRIDE;
                float d = 0.0f;
#pragma unroll
                for (int c = 0; c < 64; c++) d = fmaf(qr[c], krow[c], d);
                s[r] = d * 0.125f + slope * (float)(i - j);
            } else {
                s[r] = -INFINITY;
            }
        }

        float m = s[0];
#pragma unroll
        for (int r = 1; r < 8; r++) m = fmaxf(m, s[r]);
#pragma unroll
        for (int off = 16; off > 0; off >>= 1)
            m = fmaxf(m, __shfl_xor_sync(0xffffffffu, m, off));

        float e[8];
        float sum = 0.0f;
#pragma unroll
        for (int r = 0; r < 8; r++) { e[r] = expf(s[r] - m); sum += e[r]; }
#pragma unroll
        for (int off = 16; off > 0; off >>= 1)
            sum += __shfl_xor_sync(0xffffffffu, sum, off);
        const float inv = 1.0f / sum;

#pragma unroll
        for (int r = 0; r < 8; r++) {
            const int jl = lane + 32 * r;
            const float p = e[r] * inv;
            pw[jl] = p;
            if (attn) {
                const int j = kbase + jl;
                if (jl < nk && j <= i)
                    attn[(((size_t)(b * NHEAD + h) * TSEQ + i) * TSEQ) + j] = p;
            }
        }
        __syncwarp();

        float o0 = 0.0f, o1 = 0.0f;
        for (int j = 0; j < nk; j++) {
            const float p = pw[j];
            o0 = fmaf(p, Vs[j * KSTRIDE + lane],      o0);
            o1 = fmaf(p, Vs[j * KSTRIDE + lane + 32], o1);
        }
        float* Og = O + ((size_t)b * TSEQ + i) * CDIM + h * HDIM;
        Og[lane]      = o0;
        Og[lane + 32] = o1;
        __syncwarp();
    }
}

// ---------------------------------------------------------------------------
extern "C" void kernel_launch(void* const* d_in, const int* in_sizes, int n_in,
                              void* d_out, int out_size)
{
    const float* x  = (const float*)d_in[0];
    const float* Wq = (const float*)d_in[1];
    const float* bq = (const float*)d_in[2];
    const float* Wk = (const float*)d_in[3];
    const float* bk = (const float*)d_in[4];
    const float* Wv = (const float*)d_in[5];
    const float* bv = (const float*)d_in[6];
    const float* Wo = (const float*)d_in[7];
    const float* bo = (const float*)d_in[8];
    float* out = (float*)d_out;

    float *Qp, *Kp, *Vp, *AOp;
    cudaGetSymbolAddress((void**)&Qp,  g_Q);
    cudaGetSymbolAddress((void**)&Kp,  g_K);
    cudaGetSymbolAddress((void**)&Vp,  g_V);
    cudaGetSymbolAddress((void**)&AOp, g_AO);
    __nv_bfloat16 *xh, *xl, *aoh, *aol, *wh, *wl;
    cudaGetSymbolAddress((void**)&xh,  g_xh);
    cudaGetSymbolAddress((void**)&xl,  g_xl);
    cudaGetSymbolAddress((void**)&aoh, g_aoh);
    cudaGetSymbolAddress((void**)&aol, g_aol);
    cudaGetSymbolAddress((void**)&wh,  g_wh);
    cudaGetSymbolAddress((void**)&wl,  g_wl);

    const size_t ATT_SHM =
        (size_t)(2 * 256 * KSTRIDE + 128 * HDIM + 8 * 256) * sizeof(float);
    cudaFuncSetAttribute(attn_kernel,
                         cudaFuncAttributeMaxDynamicSharedMemorySize, (int)ATT_SHM);

    // 1) Splits: x -> (xh, xl);  W* -> transposed (wh[i], wl[i])
    const int n4 = MROWS * CDIM / 4;
    split_fp32_kernel<<<(n4 + 255) / 256, 256>>>(x, xh, xl, n4);
    {
        dim3 tb(32, 8), tg(CDIM / 32, CDIM / 32);
        split_transpose_kernel<<<tg, tb>>>(Wq, wh + 0ull * CDIM * CDIM, wl + 0ull * CDIM * CDIM);
        split_transpose_kernel<<<tg, tb>>>(Wk, wh + 1ull * CDIM * CDIM, wl + 1ull * CDIM * CDIM);
        split_transpose_kernel<<<tg, tb>>>(Wv, wh + 2ull * CDIM * CDIM, wl + 2ull * CDIM * CDIM);
        split_transpose_kernel<<<tg, tb>>>(Wo, wh + 3ull * CDIM * CDIM, wl + 3ull * CDIM * CDIM);
    }

    // 2) Q/K/V projections on HMMA tensor path
    dim3 ggrid(CDIM / 64, MROWS / 128);
    gemm_hmma_kernel<<<ggrid, 256>>>(xh, xl, wh + 0ull * CDIM * CDIM, wl + 0ull * CDIM * CDIM, bq, Qp);
    gemm_hmma_kernel<<<ggrid, 256>>>(xh, xl, wh + 1ull * CDIM * CDIM, wl + 1ull * CDIM * CDIM, bk, Kp);
    gemm_hmma_kernel<<<ggrid, 256>>>(xh, xl, wh + 2ull * CDIM * CDIM, wl + 2ull * CDIM * CDIM, bv, Vp);

    // 3) Attention (optional attn-prob output if harness compares the tuple)
    float* attn = nullptr;
    const long long out_elems = (long long)MROWS * CDIM;
    if ((long long)out_size > out_elems) {
        attn = out + out_elems;
        cudaMemsetAsync(attn, 0,
                        (size_t)BBATCH * NHEAD * TSEQ * TSEQ * sizeof(float), 0);
    }
    dim3 agrid(TSEQ / 128, NHEAD, BBATCH);
    attn_kernel<<<agrid, 256, ATT_SHM>>>(Qp, Kp, Vp, AOp, attn);

    // 4) Output projection
    split_fp32_kernel<<<(n4 + 255) / 256, 256>>>(AOp, aoh, aol, n4);
    gemm_hmma_kernel<<<ggrid, 256>>>(aoh, aol, wh + 3ull * CDIM * CDIM, wl + 3ull * CDIM * CDIM, bo, out);
}

// round 11
// speedup vs baseline: 1.9909x; 1.2420x over previous
#include <cuda_runtime.h>
#include <cuda_bf16.h>
#include <cstdint>
#include <math.h>

// Problem constants
#define CDIM   1024
#define TSEQ   2048
#define BBATCH 2
#define NHEAD  16
#define HDIM   64
#define MROWS  (BBATCH * TSEQ)   // 4096

// ---------------------------------------------------------------------------
// Scratch (__device__ globals; allocation-free rule)
// ---------------------------------------------------------------------------
__device__ float g_Q [MROWS * CDIM];
__device__ float g_K [MROWS * CDIM];
__device__ float g_V [MROWS * CDIM];
__device__ float g_AO[MROWS * CDIM];

// bf16 hi/lo splits of activations and transposed weights
__device__ __nv_bfloat16 g_xh [MROWS * CDIM];
__device__ __nv_bfloat16 g_xl [MROWS * CDIM];
__device__ __nv_bfloat16 g_aoh[MROWS * CDIM];
__device__ __nv_bfloat16 g_aol[MROWS * CDIM];
__device__ __nv_bfloat16 g_wh [4][CDIM * CDIM];  // W^T hi  [n][k]
__device__ __nv_bfloat16 g_wl [4][CDIM * CDIM];  // W^T lo  [n][k]

__device__ __forceinline__ uint32_t smem_u32(const void* p) {
    uint32_t a;
    asm("{ .reg .u64 t; cvta.to.shared.u64 t, %1; cvt.u32.u64 %0, t; }" : "=r"(a) : "l"(p));
    return a;
}

// ---------------------------------------------------------------------------
// Split/convert kernels
// ---------------------------------------------------------------------------
__global__ void split_fp32_kernel(const float* __restrict__ in,
                                  __nv_bfloat16* __restrict__ h,
                                  __nv_bfloat16* __restrict__ l, int n4)
{
    int i = blockIdx.x * 256 + threadIdx.x;
    if (i >= n4) return;
    float4 v = reinterpret_cast<const float4*>(in)[i];
    __nv_bfloat16 hx = __float2bfloat16(v.x), hy = __float2bfloat16(v.y);
    __nv_bfloat16 hz = __float2bfloat16(v.z), hw = __float2bfloat16(v.w);
    __nv_bfloat16 lx = __float2bfloat16(v.x - __bfloat162float(hx));
    __nv_bfloat16 ly = __float2bfloat16(v.y - __bfloat162float(hy));
    __nv_bfloat16 lz = __float2bfloat16(v.z - __bfloat162float(hz));
    __nv_bfloat16 lw = __float2bfloat16(v.w - __bfloat162float(hw));
    reinterpret_cast<__nv_bfloat162*>(h)[i * 2]     = __nv_bfloat162(hx, hy);
    reinterpret_cast<__nv_bfloat162*>(h)[i * 2 + 1] = __nv_bfloat162(hz, hw);
    reinterpret_cast<__nv_bfloat162*>(l)[i * 2]     = __nv_bfloat162(lx, ly);
    reinterpret_cast<__nv_bfloat162*>(l)[i * 2 + 1] = __nv_bfloat162(lz, lw);
}

// W[k][n] (1024x1024 fp32) -> Bh/Bl[n][k] bf16 (transposed split)
__global__ void split_transpose_kernel(const float* __restrict__ W,
                                       __nv_bfloat16* __restrict__ Bh,
                                       __nv_bfloat16* __restrict__ Bl)
{
    __shared__ float t[32][33];
    const int n0 = blockIdx.x * 32, k0 = blockIdx.y * 32;
    const int tx = threadIdx.x, ty = threadIdx.y;
#pragma unroll
    for (int dy = 0; dy < 32; dy += 8)
        t[ty + dy][tx] = W[(size_t)(k0 + ty + dy) * CDIM + n0 + tx];
    __syncthreads();
#pragma unroll
    for (int dy = 0; dy < 32; dy += 8) {
        const int n = n0 + ty + dy;
        const float v = t[tx][ty + dy];
        __nv_bfloat16 h = __float2bfloat16(v);
        __nv_bfloat16 l = __float2bfloat16(v - __bfloat162float(h));
        Bh[(size_t)n * CDIM + k0 + tx] = h;
        Bl[(size_t)n * CDIM + k0 + tx] = l;
    }
}

// ---------------------------------------------------------------------------
// HMMA GEMM: C[M,1024] = (Ah+Al)[M,1024] @ (Bh+Bl)^T + bias
// (unchanged — verified WIN in R6)
// ---------------------------------------------------------------------------
#define BKC     32
#define NITER   (CDIM / BKC)          // 32
#define SM_A_SZ (128 * 128)           // 16 KB
#define SM_B_SZ (64 * 128)            // 8 KB

__device__ __forceinline__ void cp_async16(uint32_t dst, const void* src) {
    asm volatile("cp.async.cg.shared.global [%0], [%1], 16;" :: "r"(dst), "l"(src));
}
__device__ __forceinline__ void cp_commit() {
    asm volatile("cp.async.commit_group;");
}
__device__ __forceinline__ void cp_wait1() {
    asm volatile("cp.async.wait_group 1;");
}

__device__ __forceinline__ void ldsm_x4(uint32_t* r, uint32_t addr) {
    asm volatile("ldmatrix.sync.aligned.m8n8.x4.shared.b16 {%0,%1,%2,%3}, [%4];"
                 : "=r"(r[0]), "=r"(r[1]), "=r"(r[2]), "=r"(r[3]) : "r"(addr));
}
__device__ __forceinline__ void mma_bf16(float* c, const uint32_t* a, const uint32_t* b) {
    asm volatile("mma.sync.aligned.m16n8k16.row.col.f32.bf16.bf16.f32 "
                 "{%0,%1,%2,%3}, {%4,%5,%6,%7}, {%8,%9}, {%0,%1,%2,%3};"
                 : "+f"(c[0]), "+f"(c[1]), "+f"(c[2]), "+f"(c[3])
                 : "r"(a[0]), "r"(a[1]), "r"(a[2]), "r"(a[3]), "r"(b[0]), "r"(b[1]));
}

__global__ __launch_bounds__(256, 2)
void gemm_hmma_kernel(const __nv_bfloat16* __restrict__ Ah,
                      const __nv_bfloat16* __restrict__ Al,
                      const __nv_bfloat16* __restrict__ Bh,
                      const __nv_bfloat16* __restrict__ Bl,
                      const float* __restrict__ bias,
                      float* __restrict__ C)
{
    __shared__ __align__(128) char smA[2][SM_A_SZ];
    __shared__ __align__(128) char smB[2][SM_B_SZ];

    const int tid  = threadIdx.x;
    const int lane = tid & 31;
    const int wrp  = tid >> 5;
    const int wm   = (wrp >> 1) * 32;
    const int wn   = (wrp & 1) * 32;
    const int bm   = blockIdx.y;
    const int bn   = blockIdx.x;

    const uint32_t sA[2] = { smem_u32(smA[0]), smem_u32(smA[1]) };
    const uint32_t sB[2] = { smem_u32(smB[0]), smem_u32(smB[1]) };

    const __nv_bfloat16* Agh = Ah + (size_t)(bm * 128) * CDIM;
    const __nv_bfloat16* Agl = Al + (size_t)(bm * 128) * CDIM;
    const __nv_bfloat16* Bgh = Bh + (size_t)(bn * 64) * CDIM;
    const __nv_bfloat16* Bgl = Bl + (size_t)(bn * 64) * CDIM;

    auto issue_stage = [&](int kI, int s) {
        if (kI < NITER) {
            const int k0 = kI * BKC;
#pragma unroll
            for (int i = 0; i < 4; i++) {
                const int idx = tid + i * 256;
                const int r = idx >> 3, c = idx & 7;
                const __nv_bfloat16* src =
                    ((c < 4) ? Agh : Agl) + (size_t)r * CDIM + k0 + (c & 3) * 8;
                cp_async16(sA[s] + r * 128 + 16 * (c ^ (r & 7)), src);
            }
#pragma unroll
            for (int i = 0; i < 2; i++) {
                const int idx = tid + i * 256;
                const int r = idx >> 3, c = idx & 7;
                const __nv_bfloat16* src =
                    ((c < 4) ? Bgh : Bgl) + (size_t)r * CDIM + k0 + (c & 3) * 8;
                cp_async16(sB[s] + r * 128 + 16 * (c ^ (r & 7)), src);
            }
        }
        cp_commit();
    };

    float acc[2][4][4];
#pragma unroll
    for (int mt = 0; mt < 2; mt++)
#pragma unroll
        for (int ng = 0; ng < 4; ng++)
#pragma unroll
            for (int j = 0; j < 4; j++) acc[mt][ng][j] = 0.0f;

    issue_stage(0, 0);
    issue_stage(1, 1);

    for (int kI = 0; kI < NITER; kI++) {
        const int s = kI & 1;
        cp_wait1();
        __syncthreads();

#pragma unroll
        for (int kk = 0; kk < 2; kk++) {
            uint32_t afr[2][2][4];
#pragma unroll
            for (int h = 0; h < 2; h++)
#pragma unroll
                for (int mt = 0; mt < 2; mt++) {
                    const int row = wm + mt * 16 + (lane & 15);
                    const int ch  = h * 4 + kk * 2 + (lane >> 4);
                    ldsm_x4(afr[h][mt], sA[s] + row * 128 + 16 * (ch ^ (row & 7)));
                }
            uint32_t bfr[2][2][4];
#pragma unroll
            for (int h = 0; h < 2; h++)
#pragma unroll
                for (int nb = 0; nb < 2; nb++) {
                    const int nrow = wn + nb * 16 + (lane & 7) + ((lane >> 4) & 1) * 8;
                    const int ch   = h * 4 + kk * 2 + ((lane >> 3) & 1);
                    ldsm_x4(bfr[h][nb], sB[s] + nrow * 128 + 16 * (ch ^ (nrow & 7)));
                }
#pragma unroll
            for (int mt = 0; mt < 2; mt++)
#pragma unroll
                for (int ng = 0; ng < 4; ng++) {
                    const uint32_t* bh2 = &bfr[0][ng >> 1][(ng & 1) * 2];
                    const uint32_t* bl2 = &bfr[1][ng >> 1][(ng & 1) * 2];
                    mma_bf16(acc[mt][ng], afr[0][mt], bh2);
                    mma_bf16(acc[mt][ng], afr[0][mt], bl2);
                    mma_bf16(acc[mt][ng], afr[1][mt], bh2);
                }
        }
        __syncthreads();
        issue_stage(kI + 2, s);
    }

    const int g = lane >> 2, tq = lane & 3;
#pragma unroll
    for (int mt = 0; mt < 2; mt++) {
#pragma unroll
        for (int ng = 0; ng < 4; ng++) {
            const int col = bn * 64 + wn + ng * 8 + tq * 2;
            const float b0 = bias[col], b1 = bias[col + 1];
            const int r0 = bm * 128 + wm + mt * 16 + g;
            float2 v0 = make_float2(acc[mt][ng][0] + b0, acc[mt][ng][1] + b1);
            float2 v1 = make_float2(acc[mt][ng][2] + b0, acc[mt][ng][3] + b1);
            *reinterpret_cast<float2*>(C + (size_t)r0 * CDIM + col)       = v0;
            *reinterpret_cast<float2*>(C + (size_t)(r0 + 8) * CDIM + col) = v1;
        }
    }
}

// ---------------------------------------------------------------------------
// Attention v2: 4-query register blocking + vectorized LDS.
// Valid keys for query i: j in [max(0,(i/128-1)*128), i]  (<=256).
// One CTA per (b, h, 128-query block). 8 warps; warp w owns queries
// [w*16, w*16+16), processed in 4 groups of 4.
// KSTRIDE=66 (even): float2 K/V loads stay 8B-aligned and conflict-free.
// ---------------------------------------------------------------------------
#define KSTRIDE 66
#define ATT_SMEM_FLOATS (2 * 256 * KSTRIDE + 128 * HDIM + 8 * 4 * 256)

__global__ __launch_bounds__(256, 1)
void attn_kernel(const float* __restrict__ Q,
                 const float* __restrict__ K,
                 const float* __restrict__ V,
                 float* __restrict__ O,
                 float* __restrict__ attn)
{
    const int qblk = blockIdx.x;
    const int h    = blockIdx.y;
    const int b    = blockIdx.z;

    const int kbase = (qblk == 0) ? 0 : (qblk - 1) * 128;
    const int nk    = (qblk == 0) ? 128 : 256;

    extern __shared__ float sh[];
    float* Ks = sh;                         // 256 x 66
    float* Vs = Ks + 256 * KSTRIDE;         // 256 x 66
    float* Qs = Vs + 256 * KSTRIDE;         // 128 x 64
    float* Ps = Qs + 128 * HDIM;            // 8 warps x 4 q x 256

    const int tid  = threadIdx.x;
    const int lane = tid & 31;
    const int w    = tid >> 5;

    // ---- Load K/V (float2 granules) and Q into SMEM ----
    const float* Kg = K + ((size_t)b * TSEQ + kbase) * CDIM + h * HDIM;
    const float* Vg = V + ((size_t)b * TSEQ + kbase) * CDIM + h * HDIM;
    for (int idx = tid; idx < nk * 32; idx += 256) {
        const int r = idx >> 5, c = (idx & 31) * 2;
        const float2 kv = *reinterpret_cast<const float2*>(Kg + (size_t)r * CDIM + c);
        const float2 vv = *reinterpret_cast<const float2*>(Vg + (size_t)r * CDIM + c);
        *reinterpret_cast<float2*>(Ks + r * KSTRIDE + c) = kv;
        *reinterpret_cast<float2*>(Vs + r * KSTRIDE + c) = vv;
    }
    const float* Qg = Q + ((size_t)b * TSEQ + qblk * 128) * CDIM + h * HDIM;
    for (int idx = tid; idx < 128 * 16; idx += 256) {
        const int r = idx >> 4, c = (idx & 15) * 4;
        *reinterpret_cast<float4*>(Qs + r * HDIM + c) =
            *reinterpret_cast<const float4*>(Qg + (size_t)r * CDIM + c);
    }
    __syncthreads();

    const float slope = exp2f(-0.5f * (float)(h + 1));
    float* pw = Ps + w * 4 * 256;

#pragma unroll 1
    for (int g = 0; g < 4; g++) {
        const int iq0 = w * 16 + g * 4;          // local first query of group
        const int i0  = qblk * 128 + iq0;        // global

        // ---- Scores: d[qi][r] = q_i . k_j  (j = kbase + lane + 32r) ----
        float s[4][8];
#pragma unroll
        for (int qi = 0; qi < 4; qi++)
#pragma unroll
            for (int r = 0; r < 8; r++) s[qi][r] = 0.0f;

#pragma unroll
        for (int ch = 0; ch < 4; ch++) {
            float q[4][16];
#pragma unroll
            for (int qi = 0; qi < 4; qi++)
#pragma unroll
                for (int c4 = 0; c4 < 4; c4++)
                    *reinterpret_cast<float4*>(&q[qi][c4 * 4]) =
                        *reinterpret_cast<const float4*>(Qs + (iq0 + qi) * HDIM + ch * 16 + c4 * 4);

#pragma unroll
            for (int r = 0; r < 8; r++) {
                const float* krow = Ks + (lane + 32 * r) * KSTRIDE + ch * 16;
#pragma unroll
                for (int c2 = 0; c2 < 8; c2++) {
                    const float2 kf = *reinterpret_cast<const float2*>(krow + c2 * 2);
#pragma unroll
                    for (int qi = 0; qi < 4; qi++) {
                        s[qi][r] = fmaf(q[qi][c2 * 2],     kf.x, s[qi][r]);
                        s[qi][r] = fmaf(q[qi][c2 * 2 + 1], kf.y, s[qi][r]);
                    }
                }
            }
        }

        // ---- Mask + ALiBi + softmax per query ----
#pragma unroll
        for (int qi = 0; qi < 4; qi++) {
            const int i = i0 + qi;
#pragma unroll
            for (int r = 0; r < 8; r++) {
                const int jl = lane + 32 * r;
                const int j  = kbase + jl;
                s[qi][r] = (jl < nk && j <= i)
                         ? s[qi][r] * 0.125f + slope * (float)(i - j)
                         : -INFINITY;
            }
            float m = s[qi][0];
#pragma unroll
            for (int r = 1; r < 8; r++) m = fmaxf(m, s[qi][r]);
#pragma unroll
            for (int off = 16; off > 0; off >>= 1)
                m = fmaxf(m, __shfl_xor_sync(0xffffffffu, m, off));

            float sum = 0.0f;
#pragma unroll
            for (int r = 0; r < 8; r++) {
                const float e = __expf(s[qi][r] - m);   // exp(-inf)=0
                s[qi][r] = e;
                sum += e;
            }
#pragma unroll
            for (int off = 16; off > 0; off >>= 1)
                sum += __shfl_xor_sync(0xffffffffu, sum, off);
            const float inv = 1.0f / sum;

#pragma unroll
            for (int r = 0; r < 8; r++) {
                const int jl = lane + 32 * r;
                const float p = s[qi][r] * inv;
                pw[qi * 256 + jl] = p;
                if (attn) {
                    const int j = kbase + jl;
                    if (jl < nk && j <= i)
                        attn[(((size_t)(b * NHEAD + h) * TSEQ + i) * TSEQ) + j] = p;
                }
            }
        }
        __syncwarp();

        // ---- PV: lane owns dims {2*lane, 2*lane+1}; V shared across 4 queries ----
        float o[4][2];
#pragma unroll
        for (int qi = 0; qi < 4; qi++) { o[qi][0] = 0.0f; o[qi][1] = 0.0f; }

#pragma unroll 2
        for (int j = 0; j < nk; j += 4) {
            const float4 p0 = *reinterpret_cast<const float4*>(pw + 0 * 256 + j);
            const float4 p1 = *reinterpret_cast<const float4*>(pw + 1 * 256 + j);
            const float4 p2 = *reinterpret_cast<const float4*>(pw + 2 * 256 + j);
            const float4 p3 = *reinterpret_cast<const float4*>(pw + 3 * 256 + j);
            const float* pp0 = &p0.x;
            const float* pp1 = &p1.x;
            const float* pp2 = &p2.x;
            const float* pp3 = &p3.x;
#pragma unroll
            for (int jj = 0; jj < 4; jj++) {
                const float2 v = *reinterpret_cast<const float2*>(
                    Vs + (j + jj) * KSTRIDE + 2 * lane);
                o[0][0] = fmaf(pp0[jj], v.x, o[0][0]);
                o[0][1] = fmaf(pp0[jj], v.y, o[0][1]);
                o[1][0] = fmaf(pp1[jj], v.x, o[1][0]);
                o[1][1] = fmaf(pp1[jj], v.y, o[1][1]);
                o[2][0] = fmaf(pp2[jj], v.x, o[2][0]);
                o[2][1] = fmaf(pp2[jj], v.y, o[2][1]);
                o[3][0] = fmaf(pp3[jj], v.x, o[3][0]);
                o[3][1] = fmaf(pp3[jj], v.y, o[3][1]);
            }
        }
#pragma unroll
        for (int qi = 0; qi < 4; qi++) {
            float* Og = O + ((size_t)b * TSEQ + i0 + qi) * CDIM + h * HDIM;
            *reinterpret_cast<float2*>(Og + 2 * lane) = make_float2(o[qi][0], o[qi][1]);
        }
        __syncwarp();
    }
}

// ---------------------------------------------------------------------------
extern "C" void kernel_launch(void* const* d_in, const int* in_sizes, int n_in,
                              void* d_out, int out_size)
{
    const float* x  = (const float*)d_in[0];
    const float* Wq = (const float*)d_in[1];
    const float* bq = (const float*)d_in[2];
    const float* Wk = (const float*)d_in[3];
    const float* bk = (const float*)d_in[4];
    const float* Wv = (const float*)d_in[5];
    const float* bv = (const float*)d_in[6];
    const float* Wo = (const float*)d_in[7];
    const float* bo = (const float*)d_in[8];
    float* out = (float*)d_out;

    float *Qp, *Kp, *Vp, *AOp;
    cudaGetSymbolAddress((void**)&Qp,  g_Q);
    cudaGetSymbolAddress((void**)&Kp,  g_K);
    cudaGetSymbolAddress((void**)&Vp,  g_V);
    cudaGetSymbolAddress((void**)&AOp, g_AO);
    __nv_bfloat16 *xh, *xl, *aoh, *aol, *wh, *wl;
    cudaGetSymbolAddress((void**)&xh,  g_xh);
    cudaGetSymbolAddress((void**)&xl,  g_xl);
    cudaGetSymbolAddress((void**)&aoh, g_aoh);
    cudaGetSymbolAddress((void**)&aol, g_aol);
    cudaGetSymbolAddress((void**)&wh,  g_wh);
    cudaGetSymbolAddress((void**)&wl,  g_wl);

    const size_t ATT_SHM = (size_t)ATT_SMEM_FLOATS * sizeof(float);
    cudaFuncSetAttribute(attn_kernel,
                         cudaFuncAttributeMaxDynamicSharedMemorySize, (int)ATT_SHM);

    // 1) Splits: x -> (xh, xl);  W* -> transposed (wh[i], wl[i])
    const int n4 = MROWS * CDIM / 4;
    split_fp32_kernel<<<(n4 + 255) / 256, 256>>>(x, xh, xl, n4);
    {
        dim3 tb(32, 8), tg(CDIM / 32, CDIM / 32);
        split_transpose_kernel<<<tg, tb>>>(Wq, wh + 0ull * CDIM * CDIM, wl + 0ull * CDIM * CDIM);
        split_transpose_kernel<<<tg, tb>>>(Wk, wh + 1ull * CDIM * CDIM, wl + 1ull * CDIM * CDIM);
        split_transpose_kernel<<<tg, tb>>>(Wv, wh + 2ull * CDIM * CDIM, wl + 2ull * CDIM * CDIM);
        split_transpose_kernel<<<tg, tb>>>(Wo, wh + 3ull * CDIM * CDIM, wl + 3ull * CDIM * CDIM);
    }

    // 2) Q/K/V projections on HMMA tensor path
    dim3 ggrid(CDIM / 64, MROWS / 128);
    gemm_hmma_kernel<<<ggrid, 256>>>(xh, xl, wh + 0ull * CDIM * CDIM, wl + 0ull * CDIM * CDIM, bq, Qp);
    gemm_hmma_kernel<<<ggrid, 256>>>(xh, xl, wh + 1ull * CDIM * CDIM, wl + 1ull * CDIM * CDIM, bk, Kp);
    gemm_hmma_kernel<<<ggrid, 256>>>(xh, xl, wh + 2ull * CDIM * CDIM, wl + 2ull * CDIM * CDIM, bv, Vp);

    // 3) Attention (optional attn-prob output if harness compares the tuple)
    float* attn = nullptr;
    const long long out_elems = (long long)MROWS * CDIM;
    if ((long long)out_size > out_elems) {
        attn = out + out_elems;
        cudaMemsetAsync(attn, 0,
                        (size_t)BBATCH * NHEAD * TSEQ * TSEQ * sizeof(float), 0);
    }
    dim3 agrid(TSEQ / 128, NHEAD, BBATCH);
    attn_kernel<<<agrid, 256, ATT_SHM>>>(Qp, Kp, Vp, AOp, attn);

    // 4) Output projection
    split_fp32_kernel<<<(n4 + 255) / 256, 256>>>(AOp, aoh, aol, n4);
    gemm_hmma_kernel<<<ggrid, 256>>>(aoh, aol, wh + 3ull * CDIM * CDIM, wl + 3ull * CDIM * CDIM, bo, out);
}